// round 2
// baseline (speedup 1.0000x reference)
#include <cuda_runtime.h>
#include <math.h>

#define DIMC   1024
#define HEADS  16
#define HD     64
#define NSEQ   1024
#define BATCH  4
#define TOK    (BATCH*NSEQ)

// ------------------------- scratch (device globals) -------------------------
__device__ float g_h1[TOK*DIMC];                                   // 16 MB
__device__ float g_qkvbuf[(size_t)TOK*3*DIMC];                     // 48 MB
__device__ float g_scores[(size_t)BATCH*HEADS*NSEQ*NSEQ];          // 256 MB
__device__ float g_attnout[TOK*DIMC];                              // 16 MB
__device__ float g_x1[TOK*DIMC];                                   // 16 MB
__device__ float g_h2[TOK*DIMC];                                   // 16 MB
__device__ float g_mlp[(size_t)TOK*4*DIMC];                        // 64 MB

// ------------------------- layernorm -------------------------
__global__ void layernorm_k(const float* __restrict__ in,
                            const float* __restrict__ g,
                            const float* __restrict__ b,
                            float* __restrict__ out)
{
    __shared__ float red[32];
    int row = blockIdx.x;
    int t   = threadIdx.x;            // 256 threads, 4 floats each
    const float4* inr = (const float4*)(in + (size_t)row*DIMC);
    float4 v = inr[t];

    float s = v.x + v.y + v.z + v.w;
    #pragma unroll
    for (int o = 16; o > 0; o >>= 1) s += __shfl_xor_sync(0xffffffffu, s, o);
    if ((t & 31) == 0) red[t >> 5] = s;
    __syncthreads();
    if (t < 32) {
        float x = (t < 8) ? red[t] : 0.f;
        #pragma unroll
        for (int o = 4; o > 0; o >>= 1) x += __shfl_xor_sync(0xffffffffu, x, o);
        if (t == 0) red[0] = x;
    }
    __syncthreads();
    float mu = red[0] * (1.0f / DIMC);

    float d0 = v.x - mu, d1 = v.y - mu, d2 = v.z - mu, d3 = v.w - mu;
    float sq = d0*d0 + d1*d1 + d2*d2 + d3*d3;
    #pragma unroll
    for (int o = 16; o > 0; o >>= 1) sq += __shfl_xor_sync(0xffffffffu, sq, o);
    __syncthreads();
    if ((t & 31) == 0) red[t >> 5] = sq;
    __syncthreads();
    if (t < 32) {
        float x = (t < 8) ? red[t] : 0.f;
        #pragma unroll
        for (int o = 4; o > 0; o >>= 1) x += __shfl_xor_sync(0xffffffffu, x, o);
        if (t == 0) red[1] = x;
    }
    __syncthreads();
    float rstd = rsqrtf(red[1] * (1.0f / DIMC) + 1e-5f);

    float4 gv = ((const float4*)g)[t];
    float4 bv = ((const float4*)b)[t];
    float4 o4;
    o4.x = d0 * rstd * gv.x + bv.x;
    o4.y = d1 * rstd * gv.y + bv.y;
    o4.z = d2 * rstd * gv.z + bv.z;
    o4.w = d3 * rstd * gv.w + bv.w;
    ((float4*)(out + (size_t)row*DIMC))[t] = o4;
}

// ------------------------- generic SGEMM, 128x128x8, 8x8/thread -------------------------
// EPI: 0 = C = A@W + bias
//      1 = C = gelu_exact(A@W + bias)
//      2 = C = resid + gate[0]*(A@W + bias)
template<int EPI>
__global__ void __launch_bounds__(256) sgemm_k(
    const float* __restrict__ A, const float* __restrict__ W,
    const float* __restrict__ bias, const float* __restrict__ resid,
    const float* __restrict__ gate, float* __restrict__ C,
    int M, int Nn, int K)
{
    __shared__ float As[8][128];
    __shared__ float Bs[8][128];

    int tid = threadIdx.x;
    int tx = tid & 15, ty = tid >> 4;
    int rowBase = blockIdx.y * 128;
    int colBase = blockIdx.x * 128;

    // A-tile load: 128 rows x 8 cols, 2 threads per row, float4 each
    int arow = tid >> 1;
    int acol = (tid & 1) * 4;
    // B-tile load: 8 rows x 128 cols, float4 each
    int brow = tid >> 5;
    int bcol = (tid & 31) * 4;

    float acc[8][8];
    #pragma unroll
    for (int i = 0; i < 8; i++)
        #pragma unroll
        for (int j = 0; j < 8; j++) acc[i][j] = 0.f;

    const float* Aptr = A + (size_t)(rowBase + arow) * K;
    for (int kk = 0; kk < K; kk += 8) {
        float4 a4 = *(const float4*)(Aptr + kk + acol);
        As[acol + 0][arow] = a4.x;
        As[acol + 1][arow] = a4.y;
        As[acol + 2][arow] = a4.z;
        As[acol + 3][arow] = a4.w;
        float4 b4 = *(const float4*)(W + (size_t)(kk + brow) * Nn + colBase + bcol);
        *(float4*)&Bs[brow][bcol] = b4;
        __syncthreads();

        #pragma unroll
        for (int k = 0; k < 8; k++) {
            float ra[8], rb[8];
            #pragma unroll
            for (int i = 0; i < 4; i++) {
                ra[i]     = As[k][ty * 4 + i];
                ra[i + 4] = As[k][64 + ty * 4 + i];
                rb[i]     = Bs[k][tx * 4 + i];
                rb[i + 4] = Bs[k][64 + tx * 4 + i];
            }
            #pragma unroll
            for (int i = 0; i < 8; i++)
                #pragma unroll
                for (int j = 0; j < 8; j++)
                    acc[i][j] += ra[i] * rb[j];
        }
        __syncthreads();
    }

    float gv = (EPI == 2) ? gate[0] : 0.f;
    #pragma unroll
    for (int ii = 0; ii < 2; ii++)
    #pragma unroll
    for (int i2 = 0; i2 < 4; i2++) {
        int r = rowBase + ii * 64 + ty * 4 + i2;
        #pragma unroll
        for (int jj = 0; jj < 2; jj++)
        #pragma unroll
        for (int j2 = 0; j2 < 4; j2++) {
            int c = colBase + jj * 64 + tx * 4 + j2;
            float v = acc[ii * 4 + i2][jj * 4 + j2] + bias[c];
            if (EPI == 1) {
                v = 0.5f * v * (1.0f + erff(v * 0.70710678118654752f));
            } else if (EPI == 2) {
                v = resid[(size_t)r * Nn + c] + gv * v;
            }
            C[(size_t)r * Nn + c] = v;
        }
    }
}

// ------------------------- attention scores: S = scale*Q K^T + relpos + mask -------------------------
__global__ void __launch_bounds__(256) attn_scores_k(
    const float* __restrict__ qkv, const float* __restrict__ rel,
    const int* __restrict__ mask, float* __restrict__ S)
{
    __shared__ float Qs[HD][65];   // [d][q]
    __shared__ float Ks[HD][65];   // [d][k]
    int bh = blockIdx.z;
    int b = bh >> 4, h = bh & 15;
    int q0 = blockIdx.y * 64, k0 = blockIdx.x * 64;
    int tid = threadIdx.x;

    int lrow = tid >> 2;
    int lcol = (tid & 3) * 16;
    {
        const float* qp = qkv + (size_t)(b*NSEQ + q0 + lrow)*3*DIMC + h*HD + lcol;
        const float* kp = qkv + (size_t)(b*NSEQ + k0 + lrow)*3*DIMC + DIMC + h*HD + lcol;
        #pragma unroll
        for (int u = 0; u < 4; u++) {
            float4 v = *(const float4*)(qp + u * 4);
            Qs[lcol + u*4 + 0][lrow] = v.x;
            Qs[lcol + u*4 + 1][lrow] = v.y;
            Qs[lcol + u*4 + 2][lrow] = v.z;
            Qs[lcol + u*4 + 3][lrow] = v.w;
            float4 w = *(const float4*)(kp + u * 4);
            Ks[lcol + u*4 + 0][lrow] = w.x;
            Ks[lcol + u*4 + 1][lrow] = w.y;
            Ks[lcol + u*4 + 2][lrow] = w.z;
            Ks[lcol + u*4 + 3][lrow] = w.w;
        }
    }
    __syncthreads();

    int tx = tid & 15, ty = tid >> 4;
    float acc[4][4];
    #pragma unroll
    for (int i = 0; i < 4; i++)
        #pragma unroll
        for (int j = 0; j < 4; j++) acc[i][j] = 0.f;

    #pragma unroll 8
    for (int d = 0; d < HD; d++) {
        float qa[4], ka[4];
        #pragma unroll
        for (int i = 0; i < 4; i++) qa[i] = Qs[d][ty * 4 + i];
        #pragma unroll
        for (int j = 0; j < 4; j++) ka[j] = Ks[d][tx * 4 + j];
        #pragma unroll
        for (int i = 0; i < 4; i++)
            #pragma unroll
            for (int j = 0; j < 4; j++)
                acc[i][j] += qa[i] * ka[j];
    }

    const float scale = 0.125f;  // 1/sqrt(64)
    #pragma unroll
    for (int i = 0; i < 4; i++) {
        int qg = q0 + ty * 4 + i;
        int mq = mask[b * NSEQ + qg];
        #pragma unroll
        for (int j = 0; j < 4; j++) {
            int kg = k0 + tx * 4 + j;
            int mk = mask[b * NSEQ + kg];
            float v = acc[i][j] * scale + rel[(size_t)(qg - kg + NSEQ - 1) * HEADS + h];
            if (!(mq && mk)) v = -1e9f;
            S[((size_t)bh * NSEQ + qg) * NSEQ + kg] = v;
        }
    }
}

// ------------------------- row softmax over 1024 -------------------------
__global__ void softmax_k(float* __restrict__ S)
{
    __shared__ float red[32];
    size_t row = blockIdx.x;
    float* p = S + row * NSEQ;
    int t = threadIdx.x;
    float4 v = ((const float4*)p)[t];

    float m = fmaxf(fmaxf(v.x, v.y), fmaxf(v.z, v.w));
    #pragma unroll
    for (int o = 16; o > 0; o >>= 1) m = fmaxf(m, __shfl_xor_sync(0xffffffffu, m, o));
    if ((t & 31) == 0) red[t >> 5] = m;
    __syncthreads();
    if (t < 32) {
        float x = (t < 8) ? red[t] : -INFINITY;
        #pragma unroll
        for (int o = 4; o > 0; o >>= 1) x = fmaxf(x, __shfl_xor_sync(0xffffffffu, x, o));
        if (t == 0) red[0] = x;
    }
    __syncthreads();
    m = red[0];

    float e0 = __expf(v.x - m), e1 = __expf(v.y - m);
    float e2 = __expf(v.z - m), e3 = __expf(v.w - m);
    float s = e0 + e1 + e2 + e3;
    #pragma unroll
    for (int o = 16; o > 0; o >>= 1) s += __shfl_xor_sync(0xffffffffu, s, o);
    __syncthreads();
    if ((t & 31) == 0) red[t >> 5] = s;
    __syncthreads();
    if (t < 32) {
        float x = (t < 8) ? red[t] : 0.f;
        #pragma unroll
        for (int o = 4; o > 0; o >>= 1) x += __shfl_xor_sync(0xffffffffu, x, o);
        if (t == 0) red[1] = x;
    }
    __syncthreads();
    float inv = 1.0f / red[1];

    float4 o4 = { e0 * inv, e1 * inv, e2 * inv, e3 * inv };
    ((float4*)p)[t] = o4;
}

// ------------------------- attn @ V -------------------------
__global__ void __launch_bounds__(256) attnv_k(
    const float* __restrict__ S, const float* __restrict__ qkv,
    float* __restrict__ out)
{
    __shared__ float Ps[16][68];   // [k][q]
    __shared__ float Vs[16][68];   // [k][d]
    int bh = blockIdx.z;
    int b = bh >> 4, h = bh & 15;
    int q0 = blockIdx.x * 64;
    int tid = threadIdx.x;
    int tx = tid & 15, ty = tid >> 4;

    float acc[4][4];
    #pragma unroll
    for (int i = 0; i < 4; i++)
        #pragma unroll
        for (int j = 0; j < 4; j++) acc[i][j] = 0.f;

    const float* Srow = S + ((size_t)bh * NSEQ + q0) * NSEQ;
    int prow = tid >> 2, pcol = (tid & 3) * 4;
    int vrow = tid >> 4, vcol = (tid & 15) * 4;

    for (int kk = 0; kk < NSEQ; kk += 16) {
        float4 p4 = *(const float4*)(Srow + (size_t)prow * NSEQ + kk + pcol);
        Ps[pcol + 0][prow] = p4.x;
        Ps[pcol + 1][prow] = p4.y;
        Ps[pcol + 2][prow] = p4.z;
        Ps[pcol + 3][prow] = p4.w;
        float4 v4 = *(const float4*)(qkv + (size_t)(b*NSEQ + kk + vrow)*3*DIMC + 2*DIMC + h*HD + vcol);
        *(float4*)&Vs[vrow][vcol] = v4;
        __syncthreads();

        #pragma unroll
        for (int k = 0; k < 16; k++) {
            float pa[4], va[4];
            #pragma unroll
            for (int i = 0; i < 4; i++) pa[i] = Ps[k][ty * 4 + i];
            #pragma unroll
            for (int j = 0; j < 4; j++) va[j] = Vs[k][tx * 4 + j];
            #pragma unroll
            for (int i = 0; i < 4; i++)
                #pragma unroll
                for (int j = 0; j < 4; j++)
                    acc[i][j] += pa[i] * va[j];
        }
        __syncthreads();
    }

    #pragma unroll
    for (int i = 0; i < 4; i++) {
        int qg = q0 + ty * 4 + i;
        #pragma unroll
        for (int j = 0; j < 4; j++) {
            int dg = tx * 4 + j;
            out[(size_t)(b * NSEQ + qg) * DIMC + h * HD + dg] = acc[i][j];
        }
    }
}

// ------------------------- launch -------------------------
extern "C" void kernel_launch(void* const* d_in, const int* in_sizes, int n_in,
                              void* d_out, int out_size)
{
    const float* x      = (const float*)d_in[0];
    const int*   mask   = (const int*)  d_in[1];
    const float* ln1_g  = (const float*)d_in[2];
    const float* ln1_b  = (const float*)d_in[3];
    const float* qkv_w  = (const float*)d_in[4];
    const float* qkv_b  = (const float*)d_in[5];
    const float* proj_w = (const float*)d_in[6];
    const float* proj_b = (const float*)d_in[7];
    const float* rel    = (const float*)d_in[8];
    const float* ln2_g  = (const float*)d_in[9];
    const float* ln2_b  = (const float*)d_in[10];
    const float* mlp_w1 = (const float*)d_in[11];
    const float* mlp_b1 = (const float*)d_in[12];
    const float* mlp_w2 = (const float*)d_in[13];
    const float* mlp_b2 = (const float*)d_in[14];
    const float* gate1  = (const float*)d_in[15];
    const float* gate2  = (const float*)d_in[16];
    float* out = (float*)d_out;

    float *h1, *qkvbuf, *sc, *ao, *x1, *h2, *mlp;
    cudaGetSymbolAddress((void**)&h1,     g_h1);
    cudaGetSymbolAddress((void**)&qkvbuf, g_qkvbuf);
    cudaGetSymbolAddress((void**)&sc,     g_scores);
    cudaGetSymbolAddress((void**)&ao,     g_attnout);
    cudaGetSymbolAddress((void**)&x1,     g_x1);
    cudaGetSymbolAddress((void**)&h2,     g_h2);
    cudaGetSymbolAddress((void**)&mlp,    g_mlp);

    // 1. LN1
    layernorm_k<<<TOK, 256>>>(x, ln1_g, ln1_b, h1);
    // 2. QKV GEMM: [4096,1024]x[1024,3072]
    sgemm_k<0><<<dim3(3*DIMC/128, TOK/128), 256>>>(h1, qkv_w, qkv_b, nullptr, nullptr,
                                                   qkvbuf, TOK, 3*DIMC, DIMC);
    // 3. scores = scale*QK^T + relpos, masked
    attn_scores_k<<<dim3(NSEQ/64, NSEQ/64, BATCH*HEADS), 256>>>(qkvbuf, rel, mask, sc);
    // 4. softmax rows
    softmax_k<<<BATCH*HEADS*NSEQ, 256>>>(sc);
    // 5. P @ V
    attnv_k<<<dim3(NSEQ/64, 1, BATCH*HEADS), 256>>>(sc, qkvbuf, ao);
    // 6. proj + residual (gate1)
    sgemm_k<2><<<dim3(DIMC/128, TOK/128), 256>>>(ao, proj_w, proj_b, x, gate1,
                                                 x1, TOK, DIMC, DIMC);
    // 7. LN2
    layernorm_k<<<TOK, 256>>>(x1, ln2_g, ln2_b, h2);
    // 8. MLP1 + exact GELU
    sgemm_k<1><<<dim3(4*DIMC/128, TOK/128), 256>>>(h2, mlp_w1, mlp_b1, nullptr, nullptr,
                                                   mlp, TOK, 4*DIMC, DIMC);
    // 9. MLP2 + residual (gate2) -> out
    sgemm_k<2><<<dim3(DIMC/128, TOK/128), 256>>>(mlp, mlp_w2, mlp_b2, x1, gate2,
                                                 out, TOK, DIMC, 4*DIMC);
}

// round 7
// speedup vs baseline: 1.1776x; 1.1776x over previous
#include <cuda_runtime.h>
#include <math.h>
#include <mma.h>

using namespace nvcuda;

#define DIMC   1024
#define HEADS  16
#define HD     64
#define NSEQ   1024
#define BATCH  4
#define TOK    (BATCH*NSEQ)

// ------------------------- scratch (device globals) -------------------------
__device__ float g_h1[TOK*DIMC];                                   // 16 MB
__device__ float g_qkvbuf[(size_t)TOK*3*DIMC];                     // 48 MB
__device__ float g_scores[(size_t)BATCH*HEADS*NSEQ*NSEQ];          // 256 MB
__device__ float g_attnout[TOK*DIMC];                              // 16 MB
__device__ float g_x1[TOK*DIMC];                                   // 16 MB
__device__ float g_h2[TOK*DIMC];                                   // 16 MB
__device__ float g_mlp[(size_t)TOK*4*DIMC];                        // 64 MB

__device__ __forceinline__ float to_tf32(float x) {
    float r;
    asm("cvt.rna.tf32.f32 %0, %1;" : "=f"(r) : "f"(x));
    return r;
}

// ------------------------- layernorm -------------------------
__global__ void layernorm_k(const float* __restrict__ in,
                            const float* __restrict__ g,
                            const float* __restrict__ b,
                            float* __restrict__ out)
{
    __shared__ float red[32];
    int row = blockIdx.x;
    int t   = threadIdx.x;            // 256 threads, 4 floats each
    const float4* inr = (const float4*)(in + (size_t)row*DIMC);
    float4 v = inr[t];

    float s = v.x + v.y + v.z + v.w;
    #pragma unroll
    for (int o = 16; o > 0; o >>= 1) s += __shfl_xor_sync(0xffffffffu, s, o);
    if ((t & 31) == 0) red[t >> 5] = s;
    __syncthreads();
    if (t < 32) {
        float x = (t < 8) ? red[t] : 0.f;
        #pragma unroll
        for (int o = 4; o > 0; o >>= 1) x += __shfl_xor_sync(0xffffffffu, x, o);
        if (t == 0) red[0] = x;
    }
    __syncthreads();
    float mu = red[0] * (1.0f / DIMC);

    float d0 = v.x - mu, d1 = v.y - mu, d2 = v.z - mu, d3 = v.w - mu;
    float sq = d0*d0 + d1*d1 + d2*d2 + d3*d3;
    #pragma unroll
    for (int o = 16; o > 0; o >>= 1) sq += __shfl_xor_sync(0xffffffffu, sq, o);
    __syncthreads();
    if ((t & 31) == 0) red[t >> 5] = sq;
    __syncthreads();
    if (t < 32) {
        float x = (t < 8) ? red[t] : 0.f;
        #pragma unroll
        for (int o = 4; o > 0; o >>= 1) x += __shfl_xor_sync(0xffffffffu, x, o);
        if (t == 0) red[1] = x;
    }
    __syncthreads();
    float rstd = rsqrtf(red[1] * (1.0f / DIMC) + 1e-5f);

    float4 gv = ((const float4*)g)[t];
    float4 bv = ((const float4*)b)[t];
    float4 o4;
    o4.x = d0 * rstd * gv.x + bv.x;
    o4.y = d1 * rstd * gv.y + bv.y;
    o4.z = d2 * rstd * gv.z + bv.z;
    o4.w = d3 * rstd * gv.w + bv.w;
    ((float4*)(out + (size_t)row*DIMC))[t] = o4;
}

// ------------------------- tf32 WMMA GEMM, 128x128 block, 8 warps -------------------------
// EPI: 0 = C = A@W + bias
//      1 = C = gelu_exact(A@W + bias)
//      2 = C = resid + gate[0]*(A@W + bias)
template<int EPI>
__global__ void __launch_bounds__(256) wgemm_k(
    const float* __restrict__ A, const float* __restrict__ W,
    const float* __restrict__ bias, const float* __restrict__ resid,
    const float* __restrict__ gate, float* __restrict__ C,
    int M, int Nn, int K)
{
    __shared__ float As[128][20];         // [m][k], ld 20 (mult of 4)
    __shared__ float Bs[16][132];         // [k][n], ld 132 (mult of 4)
    __shared__ float stage[8][16*20];     // per-warp 16x16 epilogue staging, ld 20

    int tid  = threadIdx.x;
    int warp = tid >> 5;
    int lane = tid & 31;
    int wm = warp >> 1;     // 0..3 -> rows wm*32
    int wn = warp & 1;      // 0..1 -> cols wn*64
    int rowBase = blockIdx.y * 128;
    int colBase = blockIdx.x * 128;

    wmma::fragment<wmma::accumulator, 16, 16, 8, float> fc[2][4];
    #pragma unroll
    for (int i = 0; i < 2; i++)
        #pragma unroll
        for (int j = 0; j < 4; j++)
            wmma::fill_fragment(fc[i][j], 0.0f);

    // A loader: row = tid>>1 (0..127), k0 = (tid&1)*8
    int am = tid >> 1, ak = (tid & 1) * 8;
    // B loader: k = tid>>4 (0..15), n0 = (tid&15)*8
    int bk = tid >> 4, bn = (tid & 15) * 8;

    const float* Aptr = A + (size_t)(rowBase + am) * K + ak;
    const float* Bptr = W + (size_t)bk * Nn + colBase + bn;

    for (int kk = 0; kk < K; kk += 16) {
        float4 a0 = *(const float4*)(Aptr + kk);
        float4 a1 = *(const float4*)(Aptr + kk + 4);
        As[am][ak+0] = to_tf32(a0.x); As[am][ak+1] = to_tf32(a0.y);
        As[am][ak+2] = to_tf32(a0.z); As[am][ak+3] = to_tf32(a0.w);
        As[am][ak+4] = to_tf32(a1.x); As[am][ak+5] = to_tf32(a1.y);
        As[am][ak+6] = to_tf32(a1.z); As[am][ak+7] = to_tf32(a1.w);

        float4 b0 = *(const float4*)(Bptr + (size_t)kk * Nn);
        float4 b1 = *(const float4*)(Bptr + (size_t)kk * Nn + 4);
        Bs[bk][bn+0] = to_tf32(b0.x); Bs[bk][bn+1] = to_tf32(b0.y);
        Bs[bk][bn+2] = to_tf32(b0.z); Bs[bk][bn+3] = to_tf32(b0.w);
        Bs[bk][bn+4] = to_tf32(b1.x); Bs[bk][bn+5] = to_tf32(b1.y);
        Bs[bk][bn+6] = to_tf32(b1.z); Bs[bk][bn+7] = to_tf32(b1.w);
        __syncthreads();

        #pragma unroll
        for (int ks = 0; ks < 16; ks += 8) {
            wmma::fragment<wmma::matrix_a, 16, 16, 8, wmma::precision::tf32, wmma::row_major> fa[2];
            wmma::fragment<wmma::matrix_b, 16, 16, 8, wmma::precision::tf32, wmma::row_major> fb[4];
            #pragma unroll
            for (int i = 0; i < 2; i++)
                wmma::load_matrix_sync(fa[i], &As[wm*32 + i*16][ks], 20);
            #pragma unroll
            for (int j = 0; j < 4; j++)
                wmma::load_matrix_sync(fb[j], &Bs[ks][wn*64 + j*16], 132);
            #pragma unroll
            for (int i = 0; i < 2; i++)
                #pragma unroll
                for (int j = 0; j < 4; j++)
                    wmma::mma_sync(fc[i][j], fa[i], fb[j], fc[i][j]);
        }
        __syncthreads();
    }

    // epilogue: per-warp staging of each 16x16 tile
    float gv = (EPI == 2) ? gate[0] : 0.f;
    int rr = lane >> 1;            // 0..15
    int cc = (lane & 1) * 8;       // 0 or 8
    #pragma unroll
    for (int i = 0; i < 2; i++) {
        #pragma unroll
        for (int j = 0; j < 4; j++) {
            wmma::store_matrix_sync(&stage[warp][0], fc[i][j], 20, wmma::mem_row_major);
            __syncwarp();
            int grow = rowBase + wm*32 + i*16 + rr;
            int gcol = colBase + wn*64 + j*16 + cc;
            #pragma unroll
            for (int u = 0; u < 8; u++) {
                float v = stage[warp][rr*20 + cc + u] + bias[gcol + u];
                if (EPI == 1) {
                    v = 0.5f * v * (1.0f + erff(v * 0.70710678118654752f));
                } else if (EPI == 2) {
                    v = resid[(size_t)grow * Nn + gcol + u] + gv * v;
                }
                C[(size_t)grow * Nn + gcol + u] = v;
            }
            __syncwarp();
        }
    }
}

// ------------------------- attention scores: S = scale*Q K^T + relpos + mask -------------------------
__global__ void __launch_bounds__(256) attn_scores_k(
    const float* __restrict__ qkv, const float* __restrict__ rel,
    const int* __restrict__ mask, float* __restrict__ S)
{
    __shared__ float Qs[HD][65];   // [d][q]
    __shared__ float Ks[HD][65];   // [d][k]
    int bh = blockIdx.z;
    int b = bh >> 4, h = bh & 15;
    int q0 = blockIdx.y * 64, k0 = blockIdx.x * 64;
    int tid = threadIdx.x;

    int lrow = tid >> 2;
    int lcol = (tid & 3) * 16;
    {
        const float* qp = qkv + (size_t)(b*NSEQ + q0 + lrow)*3*DIMC + h*HD + lcol;
        const float* kp = qkv + (size_t)(b*NSEQ + k0 + lrow)*3*DIMC + DIMC + h*HD + lcol;
        #pragma unroll
        for (int u = 0; u < 4; u++) {
            float4 v = *(const float4*)(qp + u * 4);
            Qs[lcol + u*4 + 0][lrow] = v.x;
            Qs[lcol + u*4 + 1][lrow] = v.y;
            Qs[lcol + u*4 + 2][lrow] = v.z;
            Qs[lcol + u*4 + 3][lrow] = v.w;
            float4 w = *(const float4*)(kp + u * 4);
            Ks[lcol + u*4 + 0][lrow] = w.x;
            Ks[lcol + u*4 + 1][lrow] = w.y;
            Ks[lcol + u*4 + 2][lrow] = w.z;
            Ks[lcol + u*4 + 3][lrow] = w.w;
        }
    }
    __syncthreads();

    int tx = tid & 15, ty = tid >> 4;
    float acc[4][4];
    #pragma unroll
    for (int i = 0; i < 4; i++)
        #pragma unroll
        for (int j = 0; j < 4; j++) acc[i][j] = 0.f;

    #pragma unroll 8
    for (int d = 0; d < HD; d++) {
        float qa[4], ka[4];
        #pragma unroll
        for (int i = 0; i < 4; i++) qa[i] = Qs[d][ty * 4 + i];
        #pragma unroll
        for (int j = 0; j < 4; j++) ka[j] = Ks[d][tx * 4 + j];
        #pragma unroll
        for (int i = 0; i < 4; i++)
            #pragma unroll
            for (int j = 0; j < 4; j++)
                acc[i][j] += qa[i] * ka[j];
    }

    const float scale = 0.125f;  // 1/sqrt(64)
    #pragma unroll
    for (int i = 0; i < 4; i++) {
        int qg = q0 + ty * 4 + i;
        int mq = mask[b * NSEQ + qg];
        #pragma unroll
        for (int j = 0; j < 4; j++) {
            int kg = k0 + tx * 4 + j;
            int mk = mask[b * NSEQ + kg];
            float v = acc[i][j] * scale + rel[(size_t)(qg - kg + NSEQ - 1) * HEADS + h];
            if (!(mq && mk)) v = -1e9f;
            S[((size_t)bh * NSEQ + qg) * NSEQ + kg] = v;
        }
    }
}

// ------------------------- row softmax over 1024 -------------------------
__global__ void softmax_k(float* __restrict__ S)
{
    __shared__ float red[32];
    size_t row = blockIdx.x;
    float* p = S + row * NSEQ;
    int t = threadIdx.x;
    float4 v = ((const float4*)p)[t];

    float m = fmaxf(fmaxf(v.x, v.y), fmaxf(v.z, v.w));
    #pragma unroll
    for (int o = 16; o > 0; o >>= 1) m = fmaxf(m, __shfl_xor_sync(0xffffffffu, m, o));
    if ((t & 31) == 0) red[t >> 5] = m;
    __syncthreads();
    if (t < 32) {
        float x = (t < 8) ? red[t] : -INFINITY;
        #pragma unroll
        for (int o = 4; o > 0; o >>= 1) x = fmaxf(x, __shfl_xor_sync(0xffffffffu, x, o));
        if (t == 0) red[0] = x;
    }
    __syncthreads();
    m = red[0];

    float e0 = __expf(v.x - m), e1 = __expf(v.y - m);
    float e2 = __expf(v.z - m), e3 = __expf(v.w - m);
    float s = e0 + e1 + e2 + e3;
    #pragma unroll
    for (int o = 16; o > 0; o >>= 1) s += __shfl_xor_sync(0xffffffffu, s, o);
    __syncthreads();
    if ((t & 31) == 0) red[t >> 5] = s;
    __syncthreads();
    if (t < 32) {
        float x = (t < 8) ? red[t] : 0.f;
        #pragma unroll
        for (int o = 4; o > 0; o >>= 1) x += __shfl_xor_sync(0xffffffffu, x, o);
        if (t == 0) red[1] = x;
    }
    __syncthreads();
    float inv = 1.0f / red[1];

    float4 o4 = { e0 * inv, e1 * inv, e2 * inv, e3 * inv };
    ((float4*)p)[t] = o4;
}

// ------------------------- attn @ V -------------------------
__global__ void __launch_bounds__(256) attnv_k(
    const float* __restrict__ S, const float* __restrict__ qkv,
    float* __restrict__ out)
{
    __shared__ float Ps[16][68];   // [k][q]
    __shared__ float Vs[16][68];   // [k][d]
    int bh = blockIdx.z;
    int b = bh >> 4, h = bh & 15;
    int q0 = blockIdx.x * 64;
    int tid = threadIdx.x;
    int tx = tid & 15, ty = tid >> 4;

    float acc[4][4];
    #pragma unroll
    for (int i = 0; i < 4; i++)
        #pragma unroll
        for (int j = 0; j < 4; j++) acc[i][j] = 0.f;

    const float* Srow = S + ((size_t)bh * NSEQ + q0) * NSEQ;
    int prow = tid >> 2, pcol = (tid & 3) * 4;
    int vrow = tid >> 4, vcol = (tid & 15) * 4;

    for (int kk = 0; kk < NSEQ; kk += 16) {
        float4 p4 = *(const float4*)(Srow + (size_t)prow * NSEQ + kk + pcol);
        Ps[pcol + 0][prow] = p4.x;
        Ps[pcol + 1][prow] = p4.y;
        Ps[pcol + 2][prow] = p4.z;
        Ps[pcol + 3][prow] = p4.w;
        float4 v4 = *(const float4*)(qkv + (size_t)(b*NSEQ + kk + vrow)*3*DIMC + 2*DIMC + h*HD + vcol);
        *(float4*)&Vs[vrow][vcol] = v4;
        __syncthreads();

        #pragma unroll
        for (int k = 0; k < 16; k++) {
            float pa[4], va[4];
            #pragma unroll
            for (int i = 0; i < 4; i++) pa[i] = Ps[k][ty * 4 + i];
            #pragma unroll
            for (int j = 0; j < 4; j++) va[j] = Vs[k][tx * 4 + j];
            #pragma unroll
            for (int i = 0; i < 4; i++)
                #pragma unroll
                for (int j = 0; j < 4; j++)
                    acc[i][j] += pa[i] * va[j];
        }
        __syncthreads();
    }

    #pragma unroll
    for (int i = 0; i < 4; i++) {
        int qg = q0 + ty * 4 + i;
        #pragma unroll
        for (int j = 0; j < 4; j++) {
            int dg = tx * 4 + j;
            out[(size_t)(b * NSEQ + qg) * DIMC + h * HD + dg] = acc[i][j];
        }
    }
}

// ------------------------- launch -------------------------
extern "C" void kernel_launch(void* const* d_in, const int* in_sizes, int n_in,
                              void* d_out, int out_size)
{
    const float* x      = (const float*)d_in[0];
    const int*   mask   = (const int*)  d_in[1];
    const float* ln1_g  = (const float*)d_in[2];
    const float* ln1_b  = (const float*)d_in[3];
    const float* qkv_w  = (const float*)d_in[4];
    const float* qkv_b  = (const float*)d_in[5];
    const float* proj_w = (const float*)d_in[6];
    const float* proj_b = (const float*)d_in[7];
    const float* rel    = (const float*)d_in[8];
    const float* ln2_g  = (const float*)d_in[9];
    const float* ln2_b  = (const float*)d_in[10];
    const float* mlp_w1 = (const float*)d_in[11];
    const float* mlp_b1 = (const float*)d_in[12];
    const float* mlp_w2 = (const float*)d_in[13];
    const float* mlp_b2 = (const float*)d_in[14];
    const float* gate1  = (const float*)d_in[15];
    const float* gate2  = (const float*)d_in[16];
    float* out = (float*)d_out;

    float *h1, *qkvbuf, *sc, *ao, *x1, *h2, *mlp;
    cudaGetSymbolAddress((void**)&h1,     g_h1);
    cudaGetSymbolAddress((void**)&qkvbuf, g_qkvbuf);
    cudaGetSymbolAddress((void**)&sc,     g_scores);
    cudaGetSymbolAddress((void**)&ao,     g_attnout);
    cudaGetSymbolAddress((void**)&x1,     g_x1);
    cudaGetSymbolAddress((void**)&h2,     g_h2);
    cudaGetSymbolAddress((void**)&mlp,    g_mlp);

    // 1. LN1
    layernorm_k<<<TOK, 256>>>(x, ln1_g, ln1_b, h1);
    // 2. QKV GEMM: [4096,1024]x[1024,3072]
    wgemm_k<0><<<dim3(3*DIMC/128, TOK/128), 256>>>(h1, qkv_w, qkv_b, nullptr, nullptr,
                                                   qkvbuf, TOK, 3*DIMC, DIMC);
    // 3. scores = scale*QK^T + relpos, masked
    attn_scores_k<<<dim3(NSEQ/64, NSEQ/64, BATCH*HEADS), 256>>>(qkvbuf, rel, mask, sc);
    // 4. softmax rows
    softmax_k<<<BATCH*HEADS*NSEQ, 256>>>(sc);
    // 5. P @ V
    attnv_k<<<dim3(NSEQ/64, 1, BATCH*HEADS), 256>>>(sc, qkvbuf, ao);
    // 6. proj + residual (gate1)
    wgemm_k<2><<<dim3(DIMC/128, TOK/128), 256>>>(ao, proj_w, proj_b, x, gate1,
                                                 x1, TOK, DIMC, DIMC);
    // 7. LN2
    layernorm_k<<<TOK, 256>>>(x1, ln2_g, ln2_b, h2);
    // 8. MLP1 + exact GELU
    wgemm_k<1><<<dim3(4*DIMC/128, TOK/128), 256>>>(h2, mlp_w1, mlp_b1, nullptr, nullptr,
                                                   mlp, TOK, 4*DIMC, DIMC);
    // 9. MLP2 + residual (gate2) -> out
    wgemm_k<2><<<dim3(DIMC/128, TOK/128), 256>>>(mlp, mlp_w2, mlp_b2, x1, gate2,
                                                 out, TOK, DIMC, 4*DIMC);
}

// round 10
// speedup vs baseline: 1.2352x; 1.0490x over previous
#include <cuda_runtime.h>
#include <cstdint>
#include <math.h>
#include <mma.h>

using namespace nvcuda;

#define DIMC   1024
#define HEADS  16
#define HD     64
#define NSEQ   1024
#define BATCH  4
#define TOK    (BATCH*NSEQ)

// GEMM tiling
#define BK       32
#define A_LD     36
#define B_LD     132
#define STAGE_F  (128*A_LD + BK*B_LD)   // floats per stage = 4608+4224 = 8832
#define SMEM_BYTES (2*STAGE_F*4)        // 70656

// ------------------------- scratch (device globals) -------------------------
__device__ float g_h1[TOK*DIMC];
__device__ float g_qkvbuf[(size_t)TOK*3*DIMC];
__device__ float g_scores[(size_t)BATCH*HEADS*NSEQ*NSEQ];
__device__ float g_attnout[TOK*DIMC];
__device__ float g_x1[TOK*DIMC];
__device__ float g_h2[TOK*DIMC];
__device__ float g_mlp[(size_t)TOK*4*DIMC];

__device__ __forceinline__ float to_tf32(float x) {
    float r;
    asm("cvt.rna.tf32.f32 %0, %1;" : "=f"(r) : "f"(x));
    return r;
}

__device__ __forceinline__ void cp_async16(uint32_t dst, const void* src) {
    asm volatile("cp.async.cg.shared.global [%0], [%1], 16;" :: "r"(dst), "l"(src));
}
__device__ __forceinline__ void cp_commit() {
    asm volatile("cp.async.commit_group;");
}
template<int N>
__device__ __forceinline__ void cp_wait() {
    asm volatile("cp.async.wait_group %0;" :: "n"(N));
}

// ------------------------- layernorm -------------------------
__global__ void layernorm_k(const float* __restrict__ in,
                            const float* __restrict__ g,
                            const float* __restrict__ b,
                            float* __restrict__ out)
{
    __shared__ float red[32];
    int row = blockIdx.x;
    int t   = threadIdx.x;
    const float4* inr = (const float4*)(in + (size_t)row*DIMC);
    float4 v = inr[t];

    float s = v.x + v.y + v.z + v.w;
    #pragma unroll
    for (int o = 16; o > 0; o >>= 1) s += __shfl_xor_sync(0xffffffffu, s, o);
    if ((t & 31) == 0) red[t >> 5] = s;
    __syncthreads();
    if (t < 32) {
        float x = (t < 8) ? red[t] : 0.f;
        #pragma unroll
        for (int o = 4; o > 0; o >>= 1) x += __shfl_xor_sync(0xffffffffu, x, o);
        if (t == 0) red[0] = x;
    }
    __syncthreads();
    float mu = red[0] * (1.0f / DIMC);

    float d0 = v.x - mu, d1 = v.y - mu, d2 = v.z - mu, d3 = v.w - mu;
    float sq = d0*d0 + d1*d1 + d2*d2 + d3*d3;
    #pragma unroll
    for (int o = 16; o > 0; o >>= 1) sq += __shfl_xor_sync(0xffffffffu, sq, o);
    __syncthreads();
    if ((t & 31) == 0) red[t >> 5] = sq;
    __syncthreads();
    if (t < 32) {
        float x = (t < 8) ? red[t] : 0.f;
        #pragma unroll
        for (int o = 4; o > 0; o >>= 1) x += __shfl_xor_sync(0xffffffffu, x, o);
        if (t == 0) red[1] = x;
    }
    __syncthreads();
    float rstd = rsqrtf(red[1] * (1.0f / DIMC) + 1e-5f);

    float4 gv = ((const float4*)g)[t];
    float4 bv = ((const float4*)b)[t];
    float4 o4;
    o4.x = d0 * rstd * gv.x + bv.x;
    o4.y = d1 * rstd * gv.y + bv.y;
    o4.z = d2 * rstd * gv.z + bv.z;
    o4.w = d3 * rstd * gv.w + bv.w;
    ((float4*)(out + (size_t)row*DIMC))[t] = o4;
}

// ------------------------- tf32 WMMA GEMM, 128x128x32, cp.async double buffer -------------------------
// EPI: 0 = C = A@W + bias ; 1 = gelu(A@W+bias) ; 2 = resid + gate*(A@W+bias)
template<int EPI>
__global__ void __launch_bounds__(256) wgemm_k(
    const float* __restrict__ A, const float* __restrict__ W,
    const float* __restrict__ bias, const float* __restrict__ resid,
    const float* __restrict__ gate, float* __restrict__ C,
    int M, int Nn, int K)
{
    extern __shared__ float smem[];
    uint32_t sbase = (uint32_t)__cvta_generic_to_shared(smem);

    int tid  = threadIdx.x;
    int warp = tid >> 5;
    int lane = tid & 31;
    int wm = warp >> 1;     // 0..3 -> rows wm*32
    int wn = warp & 1;      // 0..1 -> cols wn*64
    int rowBase = blockIdx.y * 128;
    int colBase = blockIdx.x * 128;

    wmma::fragment<wmma::accumulator, 16, 16, 8, float> fc[2][4];
    #pragma unroll
    for (int i = 0; i < 2; i++)
        #pragma unroll
        for (int j = 0; j < 4; j++)
            wmma::fill_fragment(fc[i][j], 0.0f);

    // loader index precompute (4 A-chunks + 4 B-chunks of 16B per thread)
    int ar[4], ac[4], br4[4], bc4[4];
    #pragma unroll
    for (int i = 0; i < 4; i++) {
        int c = tid + i * 256;
        ar[i] = c >> 3;            // 0..127
        ac[i] = (c & 7) * 4;       // 0..28
        br4[i] = c >> 5;           // 0..31
        bc4[i] = (c & 31) * 4;     // 0..124
    }

    const int T = K / BK;

    // prologue: stage 0
    {
        #pragma unroll
        for (int i = 0; i < 4; i++) {
            cp_async16(sbase + (ar[i]*A_LD + ac[i])*4,
                       A + (size_t)(rowBase + ar[i]) * K + ac[i]);
        }
        #pragma unroll
        for (int i = 0; i < 4; i++) {
            cp_async16(sbase + (128*A_LD + br4[i]*B_LD + bc4[i])*4,
                       W + (size_t)br4[i] * Nn + colBase + bc4[i]);
        }
        cp_commit();
    }

    for (int t = 0; t < T; t++) {
        int cur = t & 1;
        if (t + 1 < T) {
            int k0 = (t + 1) * BK;
            uint32_t stg = sbase + (uint32_t)(((t + 1) & 1) * STAGE_F * 4);
            #pragma unroll
            for (int i = 0; i < 4; i++) {
                cp_async16(stg + (ar[i]*A_LD + ac[i])*4,
                           A + (size_t)(rowBase + ar[i]) * K + k0 + ac[i]);
            }
            #pragma unroll
            for (int i = 0; i < 4; i++) {
                cp_async16(stg + (128*A_LD + br4[i]*B_LD + bc4[i])*4,
                           W + (size_t)(k0 + br4[i]) * Nn + colBase + bc4[i]);
            }
            cp_commit();
            cp_wait<1>();
        } else {
            cp_commit();
            cp_wait<0>();
        }
        __syncthreads();

        const float* As = smem + cur * STAGE_F;
        const float* Bs = As + 128 * A_LD;

        #pragma unroll
        for (int ks = 0; ks < BK; ks += 8) {
            wmma::fragment<wmma::matrix_a, 16, 16, 8, wmma::precision::tf32, wmma::row_major> fa[2];
            wmma::fragment<wmma::matrix_b, 16, 16, 8, wmma::precision::tf32, wmma::row_major> fb[4];
            #pragma unroll
            for (int i = 0; i < 2; i++) {
                wmma::load_matrix_sync(fa[i], As + (wm*32 + i*16)*A_LD + ks, A_LD);
                #pragma unroll
                for (int e = 0; e < fa[i].num_elements; e++)
                    fa[i].x[e] = to_tf32(fa[i].x[e]);
            }
            #pragma unroll
            for (int j = 0; j < 4; j++) {
                wmma::load_matrix_sync(fb[j], Bs + ks*B_LD + wn*64 + j*16, B_LD);
                #pragma unroll
                for (int e = 0; e < fb[j].num_elements; e++)
                    fb[j].x[e] = to_tf32(fb[j].x[e]);
            }
            #pragma unroll
            for (int i = 0; i < 2; i++)
                #pragma unroll
                for (int j = 0; j < 4; j++)
                    wmma::mma_sync(fc[i][j], fa[i], fb[j], fc[i][j]);
        }
        __syncthreads();
    }

    // epilogue: per-warp 16x16 staging (reuse pipeline smem)
    float* stage = smem + warp * 320;      // 16x20 per warp
    float gv = (EPI == 2) ? gate[0] : 0.f;
    int rr = lane >> 1;
    int cc = (lane & 1) * 8;
    #pragma unroll
    for (int i = 0; i < 2; i++) {
        #pragma unroll
        for (int j = 0; j < 4; j++) {
            wmma::store_matrix_sync(stage, fc[i][j], 20, wmma::mem_row_major);
            __syncwarp();
            int grow = rowBase + wm*32 + i*16 + rr;
            int gcol = colBase + wn*64 + j*16 + cc;
            #pragma unroll
            for (int u = 0; u < 8; u++) {
                float v = stage[rr*20 + cc + u] + bias[gcol + u];
                if (EPI == 1) {
                    v = 0.5f * v * (1.0f + erff(v * 0.70710678118654752f));
                } else if (EPI == 2) {
                    v = resid[(size_t)grow * Nn + gcol + u] + gv * v;
                }
                C[(size_t)grow * Nn + gcol + u] = v;
            }
            __syncwarp();
        }
    }
}

// ------------------------- attention scores: S = scale*Q K^T + relpos + mask -------------------------
__global__ void __launch_bounds__(256) attn_scores_k(
    const float* __restrict__ qkv, const float* __restrict__ rel,
    const int* __restrict__ mask, float* __restrict__ S)
{
    __shared__ float Qs[HD][65];
    __shared__ float Ks[HD][65];
    int bh = blockIdx.z;
    int b = bh >> 4, h = bh & 15;
    int q0 = blockIdx.y * 64, k0 = blockIdx.x * 64;
    int tid = threadIdx.x;

    int lrow = tid >> 2;
    int lcol = (tid & 3) * 16;
    {
        const float* qp = qkv + (size_t)(b*NSEQ + q0 + lrow)*3*DIMC + h*HD + lcol;
        const float* kp = qkv + (size_t)(b*NSEQ + k0 + lrow)*3*DIMC + DIMC + h*HD + lcol;
        #pragma unroll
        for (int u = 0; u < 4; u++) {
            float4 v = *(const float4*)(qp + u * 4);
            Qs[lcol + u*4 + 0][lrow] = v.x;
            Qs[lcol + u*4 + 1][lrow] = v.y;
            Qs[lcol + u*4 + 2][lrow] = v.z;
            Qs[lcol + u*4 + 3][lrow] = v.w;
            float4 w = *(const float4*)(kp + u * 4);
            Ks[lcol + u*4 + 0][lrow] = w.x;
            Ks[lcol + u*4 + 1][lrow] = w.y;
            Ks[lcol + u*4 + 2][lrow] = w.z;
            Ks[lcol + u*4 + 3][lrow] = w.w;
        }
    }
    __syncthreads();

    int tx = tid & 15, ty = tid >> 4;
    float acc[4][4];
    #pragma unroll
    for (int i = 0; i < 4; i++)
        #pragma unroll
        for (int j = 0; j < 4; j++) acc[i][j] = 0.f;

    #pragma unroll 8
    for (int d = 0; d < HD; d++) {
        float qa[4], ka[4];
        #pragma unroll
        for (int i = 0; i < 4; i++) qa[i] = Qs[d][ty * 4 + i];
        #pragma unroll
        for (int j = 0; j < 4; j++) ka[j] = Ks[d][tx * 4 + j];
        #pragma unroll
        for (int i = 0; i < 4; i++)
            #pragma unroll
            for (int j = 0; j < 4; j++)
                acc[i][j] += qa[i] * ka[j];
    }

    const float scale = 0.125f;
    #pragma unroll
    for (int i = 0; i < 4; i++) {
        int qg = q0 + ty * 4 + i;
        int mq = mask[b * NSEQ + qg];
        #pragma unroll
        for (int j = 0; j < 4; j++) {
            int kg = k0 + tx * 4 + j;
            int mk = mask[b * NSEQ + kg];
            float v = acc[i][j] * scale + rel[(size_t)(qg - kg + NSEQ - 1) * HEADS + h];
            if (!(mq && mk)) v = -1e9f;
            S[((size_t)bh * NSEQ + qg) * NSEQ + kg] = v;
        }
    }
}

// ------------------------- row softmax over 1024 -------------------------
__global__ void softmax_k(float* __restrict__ S)
{
    __shared__ float red[32];
    size_t row = blockIdx.x;
    float* p = S + row * NSEQ;
    int t = threadIdx.x;
    float4 v = ((const float4*)p)[t];

    float m = fmaxf(fmaxf(v.x, v.y), fmaxf(v.z, v.w));
    #pragma unroll
    for (int o = 16; o > 0; o >>= 1) m = fmaxf(m, __shfl_xor_sync(0xffffffffu, m, o));
    if ((t & 31) == 0) red[t >> 5] = m;
    __syncthreads();
    if (t < 32) {
        float x = (t < 8) ? red[t] : -INFINITY;
        #pragma unroll
        for (int o = 4; o > 0; o >>= 1) x = fmaxf(x, __shfl_xor_sync(0xffffffffu, x, o));
        if (t == 0) red[0] = x;
    }
    __syncthreads();
    m = red[0];

    float e0 = __expf(v.x - m), e1 = __expf(v.y - m);
    float e2 = __expf(v.z - m), e3 = __expf(v.w - m);
    float s = e0 + e1 + e2 + e3;
    #pragma unroll
    for (int o = 16; o > 0; o >>= 1) s += __shfl_xor_sync(0xffffffffu, s, o);
    __syncthreads();
    if ((t & 31) == 0) red[t >> 5] = s;
    __syncthreads();
    if (t < 32) {
        float x = (t < 8) ? red[t] : 0.f;
        #pragma unroll
        for (int o = 4; o > 0; o >>= 1) x += __shfl_xor_sync(0xffffffffu, x, o);
        if (t == 0) red[1] = x;
    }
    __syncthreads();
    float inv = 1.0f / red[1];

    float4 o4 = { e0 * inv, e1 * inv, e2 * inv, e3 * inv };
    ((float4*)p)[t] = o4;
}

// ------------------------- attn @ V -------------------------
__global__ void __launch_bounds__(256) attnv_k(
    const float* __restrict__ S, const float* __restrict__ qkv,
    float* __restrict__ out)
{
    __shared__ float Ps[16][68];
    __shared__ float Vs[16][68];
    int bh = blockIdx.z;
    int b = bh >> 4, h = bh & 15;
    int q0 = blockIdx.x * 64;
    int tid = threadIdx.x;
    int tx = tid & 15, ty = tid >> 4;

    float acc[4][4];
    #pragma unroll
    for (int i = 0; i < 4; i++)
        #pragma unroll
        for (int j = 0; j < 4; j++) acc[i][j] = 0.f;

    const float* Srow = S + ((size_t)bh * NSEQ + q0) * NSEQ;
    int prow = tid >> 2, pcol = (tid & 3) * 4;
    int vrow = tid >> 4, vcol = (tid & 15) * 4;

    for (int kk = 0; kk < NSEQ; kk += 16) {
        float4 p4 = *(const float4*)(Srow + (size_t)prow * NSEQ + kk + pcol);
        Ps[pcol + 0][prow] = p4.x;
        Ps[pcol + 1][prow] = p4.y;
        Ps[pcol + 2][prow] = p4.z;
        Ps[pcol + 3][prow] = p4.w;
        float4 v4 = *(const float4*)(qkv + (size_t)(b*NSEQ + kk + vrow)*3*DIMC + 2*DIMC + h*HD + vcol);
        *(float4*)&Vs[vrow][vcol] = v4;
        __syncthreads();

        #pragma unroll
        for (int k = 0; k < 16; k++) {
            float pa[4], va[4];
            #pragma unroll
            for (int i = 0; i < 4; i++) pa[i] = Ps[k][ty * 4 + i];
            #pragma unroll
            for (int j = 0; j < 4; j++) va[j] = Vs[k][tx * 4 + j];
            #pragma unroll
            for (int i = 0; i < 4; i++)
                #pragma unroll
                for (int j = 0; j < 4; j++)
                    acc[i][j] += pa[i] * va[j];
        }
        __syncthreads();
    }

    #pragma unroll
    for (int i = 0; i < 4; i++) {
        int qg = q0 + ty * 4 + i;
        #pragma unroll
        for (int j = 0; j < 4; j++) {
            int dg = tx * 4 + j;
            out[(size_t)(b * NSEQ + qg) * DIMC + h * HD + dg] = acc[i][j];
        }
    }
}

// ------------------------- launch -------------------------
extern "C" void kernel_launch(void* const* d_in, const int* in_sizes, int n_in,
                              void* d_out, int out_size)
{
    const float* x      = (const float*)d_in[0];
    const int*   mask   = (const int*)  d_in[1];
    const float* ln1_g  = (const float*)d_in[2];
    const float* ln1_b  = (const float*)d_in[3];
    const float* qkv_w  = (const float*)d_in[4];
    const float* qkv_b  = (const float*)d_in[5];
    const float* proj_w = (const float*)d_in[6];
    const float* proj_b = (const float*)d_in[7];
    const float* rel    = (const float*)d_in[8];
    const float* ln2_g  = (const float*)d_in[9];
    const float* ln2_b  = (const float*)d_in[10];
    const float* mlp_w1 = (const float*)d_in[11];
    const float* mlp_b1 = (const float*)d_in[12];
    const float* mlp_w2 = (const float*)d_in[13];
    const float* mlp_b2 = (const float*)d_in[14];
    const float* gate1  = (const float*)d_in[15];
    const float* gate2  = (const float*)d_in[16];
    float* out = (float*)d_out;

    float *h1, *qkvbuf, *sc, *ao, *x1, *h2, *mlp;
    cudaGetSymbolAddress((void**)&h1,     g_h1);
    cudaGetSymbolAddress((void**)&qkvbuf, g_qkvbuf);
    cudaGetSymbolAddress((void**)&sc,     g_scores);
    cudaGetSymbolAddress((void**)&ao,     g_attnout);
    cudaGetSymbolAddress((void**)&x1,     g_x1);
    cudaGetSymbolAddress((void**)&h2,     g_h2);
    cudaGetSymbolAddress((void**)&mlp,    g_mlp);

    cudaFuncSetAttribute(wgemm_k<0>, cudaFuncAttributeMaxDynamicSharedMemorySize, SMEM_BYTES);
    cudaFuncSetAttribute(wgemm_k<1>, cudaFuncAttributeMaxDynamicSharedMemorySize, SMEM_BYTES);
    cudaFuncSetAttribute(wgemm_k<2>, cudaFuncAttributeMaxDynamicSharedMemorySize, SMEM_BYTES);

    // 1. LN1
    layernorm_k<<<TOK, 256>>>(x, ln1_g, ln1_b, h1);
    // 2. QKV GEMM
    wgemm_k<0><<<dim3(3*DIMC/128, TOK/128), 256, SMEM_BYTES>>>(h1, qkv_w, qkv_b, nullptr, nullptr,
                                                               qkvbuf, TOK, 3*DIMC, DIMC);
    // 3. scores
    attn_scores_k<<<dim3(NSEQ/64, NSEQ/64, BATCH*HEADS), 256>>>(qkvbuf, rel, mask, sc);
    // 4. softmax
    softmax_k<<<BATCH*HEADS*NSEQ, 256>>>(sc);
    // 5. P @ V
    attnv_k<<<dim3(NSEQ/64, 1, BATCH*HEADS), 256>>>(sc, qkvbuf, ao);
    // 6. proj + residual (gate1)
    wgemm_k<2><<<dim3(DIMC/128, TOK/128), 256, SMEM_BYTES>>>(ao, proj_w, proj_b, x, gate1,
                                                             x1, TOK, DIMC, DIMC);
    // 7. LN2
    layernorm_k<<<TOK, 256>>>(x1, ln2_g, ln2_b, h2);
    // 8. MLP1 + GELU
    wgemm_k<1><<<dim3(4*DIMC/128, TOK/128), 256, SMEM_BYTES>>>(h2, mlp_w1, mlp_b1, nullptr, nullptr,
                                                               mlp, TOK, 4*DIMC, DIMC);
    // 9. MLP2 + residual (gate2) -> out
    wgemm_k<2><<<dim3(DIMC/128, TOK/128), 256, SMEM_BYTES>>>(mlp, mlp_w2, mlp_b2, x1, gate2,
                                                             out, TOK, DIMC, 4*DIMC);
}

// round 11
// speedup vs baseline: 1.3702x; 1.1093x over previous
#include <cuda_runtime.h>
#include <cstdint>
#include <math.h>
#include <mma.h>

using namespace nvcuda;

#define DIMC   1024
#define HEADS  16
#define HD     64
#define NSEQ   1024
#define BATCH  4
#define TOK    (BATCH*NSEQ)

// GEMM tiling
#define BK       32
#define A_LD     36
#define B_LD     132
#define STAGE_F  (128*A_LD + BK*B_LD)   // floats per stage = 4608+4224 = 8832
#define SMEM_BYTES (2*STAGE_F*4)        // 70656

// ------------------------- scratch (device globals) -------------------------
__device__ float g_h1[TOK*DIMC];
__device__ float g_qkvbuf[(size_t)TOK*3*DIMC];
__device__ float g_scores[(size_t)BATCH*HEADS*NSEQ*NSEQ];
__device__ float g_attnout[TOK*DIMC];
__device__ float g_x1[TOK*DIMC];
__device__ float g_h2[TOK*DIMC];
__device__ float g_mlp[(size_t)TOK*4*DIMC];
__device__ float g_wr[12582912];   // tf32-rounded weights: qkv|proj|w1|w2

#define WR_QKV  0
#define WR_PROJ 3145728
#define WR_W1   4194304
#define WR_W2   8388608

__device__ __forceinline__ float to_tf32(float x) {
    float r;
    asm("cvt.rna.tf32.f32 %0, %1;" : "=f"(r) : "f"(x));
    return r;
}

__device__ __forceinline__ void cp_async16(uint32_t dst, const void* src) {
    asm volatile("cp.async.cg.shared.global [%0], [%1], 16;" :: "r"(dst), "l"(src));
}
__device__ __forceinline__ void cp_commit() {
    asm volatile("cp.async.commit_group;");
}
template<int N>
__device__ __forceinline__ void cp_wait() {
    asm volatile("cp.async.wait_group %0;" :: "n"(N));
}

// ------------------------- tf32 rounding copy (weights, once per replay) -------------------------
__global__ void round_k(const float* __restrict__ src, float* __restrict__ dst)
{
    int i = blockIdx.x * 256 + threadIdx.x;
    float4 v = ((const float4*)src)[i];
    v.x = to_tf32(v.x); v.y = to_tf32(v.y); v.z = to_tf32(v.z); v.w = to_tf32(v.w);
    ((float4*)dst)[i] = v;
}

// ------------------------- layernorm (output rounded to tf32) -------------------------
__global__ void layernorm_k(const float* __restrict__ in,
                            const float* __restrict__ g,
                            const float* __restrict__ b,
                            float* __restrict__ out)
{
    __shared__ float red[32];
    int row = blockIdx.x;
    int t   = threadIdx.x;
    const float4* inr = (const float4*)(in + (size_t)row*DIMC);
    float4 v = inr[t];

    float s = v.x + v.y + v.z + v.w;
    #pragma unroll
    for (int o = 16; o > 0; o >>= 1) s += __shfl_xor_sync(0xffffffffu, s, o);
    if ((t & 31) == 0) red[t >> 5] = s;
    __syncthreads();
    if (t < 32) {
        float x = (t < 8) ? red[t] : 0.f;
        #pragma unroll
        for (int o = 4; o > 0; o >>= 1) x += __shfl_xor_sync(0xffffffffu, x, o);
        if (t == 0) red[0] = x;
    }
    __syncthreads();
    float mu = red[0] * (1.0f / DIMC);

    float d0 = v.x - mu, d1 = v.y - mu, d2 = v.z - mu, d3 = v.w - mu;
    float sq = d0*d0 + d1*d1 + d2*d2 + d3*d3;
    #pragma unroll
    for (int o = 16; o > 0; o >>= 1) sq += __shfl_xor_sync(0xffffffffu, sq, o);
    __syncthreads();
    if ((t & 31) == 0) red[t >> 5] = sq;
    __syncthreads();
    if (t < 32) {
        float x = (t < 8) ? red[t] : 0.f;
        #pragma unroll
        for (int o = 4; o > 0; o >>= 1) x += __shfl_xor_sync(0xffffffffu, x, o);
        if (t == 0) red[1] = x;
    }
    __syncthreads();
    float rstd = rsqrtf(red[1] * (1.0f / DIMC) + 1e-5f);

    float4 gv = ((const float4*)g)[t];
    float4 bv = ((const float4*)b)[t];
    float4 o4;
    o4.x = to_tf32(d0 * rstd * gv.x + bv.x);
    o4.y = to_tf32(d1 * rstd * gv.y + bv.y);
    o4.z = to_tf32(d2 * rstd * gv.z + bv.z);
    o4.w = to_tf32(d3 * rstd * gv.w + bv.w);
    ((float4*)(out + (size_t)row*DIMC))[t] = o4;
}

// ------------------------- tf32 WMMA GEMM, 128x128x32, cp.async double buffer -------------------------
// Inputs A and W must already be tf32-rounded.
// EPI: 0 = C = A@W + bias ; 1 = tf32(gelu(A@W+bias)) ; 2 = resid + gate*(A@W+bias)
template<int EPI>
__global__ void __launch_bounds__(256, 2) wgemm_k(
    const float* __restrict__ A, const float* __restrict__ W,
    const float* __restrict__ bias, const float* __restrict__ resid,
    const float* __restrict__ gate, float* __restrict__ C,
    int M, int Nn, int K)
{
    extern __shared__ float smem[];
    uint32_t sbase = (uint32_t)__cvta_generic_to_shared(smem);

    int tid  = threadIdx.x;
    int warp = tid >> 5;
    int lane = tid & 31;
    int wm = warp >> 1;     // 0..3 -> rows wm*32
    int wn = warp & 1;      // 0..1 -> cols wn*64
    int rowBase = blockIdx.y * 128;
    int colBase = blockIdx.x * 128;

    wmma::fragment<wmma::accumulator, 16, 16, 8, float> fc[2][4];
    #pragma unroll
    for (int i = 0; i < 2; i++)
        #pragma unroll
        for (int j = 0; j < 4; j++)
            wmma::fill_fragment(fc[i][j], 0.0f);

    // loader index precompute (4 A-chunks + 4 B-chunks of 16B per thread)
    int ar[4], ac[4], br4[4], bc4[4];
    #pragma unroll
    for (int i = 0; i < 4; i++) {
        int c = tid + i * 256;
        ar[i] = c >> 3;            // 0..127
        ac[i] = (c & 7) * 4;       // 0..28
        br4[i] = c >> 5;           // 0..31
        bc4[i] = (c & 31) * 4;     // 0..124
    }

    const int T = K / BK;

    // prologue: stage 0
    {
        #pragma unroll
        for (int i = 0; i < 4; i++) {
            cp_async16(sbase + (ar[i]*A_LD + ac[i])*4,
                       A + (size_t)(rowBase + ar[i]) * K + ac[i]);
        }
        #pragma unroll
        for (int i = 0; i < 4; i++) {
            cp_async16(sbase + (128*A_LD + br4[i]*B_LD + bc4[i])*4,
                       W + (size_t)br4[i] * Nn + colBase + bc4[i]);
        }
        cp_commit();
    }

    for (int t = 0; t < T; t++) {
        int cur = t & 1;
        if (t + 1 < T) {
            int k0 = (t + 1) * BK;
            uint32_t stg = sbase + (uint32_t)(((t + 1) & 1) * STAGE_F * 4);
            #pragma unroll
            for (int i = 0; i < 4; i++) {
                cp_async16(stg + (ar[i]*A_LD + ac[i])*4,
                           A + (size_t)(rowBase + ar[i]) * K + k0 + ac[i]);
            }
            #pragma unroll
            for (int i = 0; i < 4; i++) {
                cp_async16(stg + (128*A_LD + br4[i]*B_LD + bc4[i])*4,
                           W + (size_t)(k0 + br4[i]) * Nn + colBase + bc4[i]);
            }
            cp_commit();
            cp_wait<1>();
        } else {
            cp_commit();
            cp_wait<0>();
        }
        __syncthreads();

        const float* As = smem + cur * STAGE_F;
        const float* Bs = As + 128 * A_LD;

        #pragma unroll
        for (int ks = 0; ks < BK; ks += 8) {
            wmma::fragment<wmma::matrix_a, 16, 16, 8, wmma::precision::tf32, wmma::row_major> fa[2];
            wmma::fragment<wmma::matrix_b, 16, 16, 8, wmma::precision::tf32, wmma::row_major> fb[4];
            #pragma unroll
            for (int i = 0; i < 2; i++)
                wmma::load_matrix_sync(fa[i], As + (wm*32 + i*16)*A_LD + ks, A_LD);
            #pragma unroll
            for (int j = 0; j < 4; j++)
                wmma::load_matrix_sync(fb[j], Bs + ks*B_LD + wn*64 + j*16, B_LD);
            #pragma unroll
            for (int i = 0; i < 2; i++)
                #pragma unroll
                for (int j = 0; j < 4; j++)
                    wmma::mma_sync(fc[i][j], fa[i], fb[j], fc[i][j]);
        }
        __syncthreads();
    }

    // epilogue: per-warp 16x16 staging (reuse pipeline smem)
    float* stage = smem + warp * 320;      // 16x20 per warp
    float gv = (EPI == 2) ? gate[0] : 0.f;
    int rr = lane >> 1;
    int cc = (lane & 1) * 8;
    #pragma unroll
    for (int i = 0; i < 2; i++) {
        #pragma unroll
        for (int j = 0; j < 4; j++) {
            wmma::store_matrix_sync(stage, fc[i][j], 20, wmma::mem_row_major);
            __syncwarp();
            int grow = rowBase + wm*32 + i*16 + rr;
            int gcol = colBase + wn*64 + j*16 + cc;
            #pragma unroll
            for (int u = 0; u < 8; u++) {
                float v = stage[rr*20 + cc + u] + bias[gcol + u];
                if (EPI == 1) {
                    v = to_tf32(0.5f * v * (1.0f + erff(v * 0.70710678118654752f)));
                } else if (EPI == 2) {
                    v = resid[(size_t)grow * Nn + gcol + u] + gv * v;
                }
                C[(size_t)grow * Nn + gcol + u] = v;
            }
            __syncwarp();
        }
    }
}

// ------------------------- attention scores: S = scale*Q K^T + relpos + mask -------------------------
__global__ void __launch_bounds__(256) attn_scores_k(
    const float* __restrict__ qkv, const float* __restrict__ rel,
    const int* __restrict__ mask, float* __restrict__ S)
{
    __shared__ float Qs[HD][65];
    __shared__ float Ks[HD][65];
    int bh = blockIdx.z;
    int b = bh >> 4, h = bh & 15;
    int q0 = blockIdx.y * 64, k0 = blockIdx.x * 64;
    int tid = threadIdx.x;

    int lrow = tid >> 2;
    int lcol = (tid & 3) * 16;
    {
        const float* qp = qkv + (size_t)(b*NSEQ + q0 + lrow)*3*DIMC + h*HD + lcol;
        const float* kp = qkv + (size_t)(b*NSEQ + k0 + lrow)*3*DIMC + DIMC + h*HD + lcol;
        #pragma unroll
        for (int u = 0; u < 4; u++) {
            float4 v = *(const float4*)(qp + u * 4);
            Qs[lcol + u*4 + 0][lrow] = v.x;
            Qs[lcol + u*4 + 1][lrow] = v.y;
            Qs[lcol + u*4 + 2][lrow] = v.z;
            Qs[lcol + u*4 + 3][lrow] = v.w;
            float4 w = *(const float4*)(kp + u * 4);
            Ks[lcol + u*4 + 0][lrow] = w.x;
            Ks[lcol + u*4 + 1][lrow] = w.y;
            Ks[lcol + u*4 + 2][lrow] = w.z;
            Ks[lcol + u*4 + 3][lrow] = w.w;
        }
    }
    __syncthreads();

    int tx = tid & 15, ty = tid >> 4;
    float acc[4][4];
    #pragma unroll
    for (int i = 0; i < 4; i++)
        #pragma unroll
        for (int j = 0; j < 4; j++) acc[i][j] = 0.f;

    #pragma unroll 8
    for (int d = 0; d < HD; d++) {
        float qa[4], ka[4];
        #pragma unroll
        for (int i = 0; i < 4; i++) qa[i] = Qs[d][ty * 4 + i];
        #pragma unroll
        for (int j = 0; j < 4; j++) ka[j] = Ks[d][tx * 4 + j];
        #pragma unroll
        for (int i = 0; i < 4; i++)
            #pragma unroll
            for (int j = 0; j < 4; j++)
                acc[i][j] += qa[i] * ka[j];
    }

    const float scale = 0.125f;
    #pragma unroll
    for (int i = 0; i < 4; i++) {
        int qg = q0 + ty * 4 + i;
        int mq = mask[b * NSEQ + qg];
        #pragma unroll
        for (int j = 0; j < 4; j++) {
            int kg = k0 + tx * 4 + j;
            int mk = mask[b * NSEQ + kg];
            float v = acc[i][j] * scale + rel[(size_t)(qg - kg + NSEQ - 1) * HEADS + h];
            if (!(mq && mk)) v = -1e9f;
            S[((size_t)bh * NSEQ + qg) * NSEQ + kg] = v;
        }
    }
}

// ------------------------- row softmax over 1024 -------------------------
__global__ void softmax_k(float* __restrict__ S)
{
    __shared__ float red[32];
    size_t row = blockIdx.x;
    float* p = S + row * NSEQ;
    int t = threadIdx.x;
    float4 v = ((const float4*)p)[t];

    float m = fmaxf(fmaxf(v.x, v.y), fmaxf(v.z, v.w));
    #pragma unroll
    for (int o = 16; o > 0; o >>= 1) m = fmaxf(m, __shfl_xor_sync(0xffffffffu, m, o));
    if ((t & 31) == 0) red[t >> 5] = m;
    __syncthreads();
    if (t < 32) {
        float x = (t < 8) ? red[t] : -INFINITY;
        #pragma unroll
        for (int o = 4; o > 0; o >>= 1) x = fmaxf(x, __shfl_xor_sync(0xffffffffu, x, o));
        if (t == 0) red[0] = x;
    }
    __syncthreads();
    m = red[0];

    float e0 = __expf(v.x - m), e1 = __expf(v.y - m);
    float e2 = __expf(v.z - m), e3 = __expf(v.w - m);
    float s = e0 + e1 + e2 + e3;
    #pragma unroll
    for (int o = 16; o > 0; o >>= 1) s += __shfl_xor_sync(0xffffffffu, s, o);
    __syncthreads();
    if ((t & 31) == 0) red[t >> 5] = s;
    __syncthreads();
    if (t < 32) {
        float x = (t < 8) ? red[t] : 0.f;
        #pragma unroll
        for (int o = 4; o > 0; o >>= 1) x += __shfl_xor_sync(0xffffffffu, x, o);
        if (t == 0) red[1] = x;
    }
    __syncthreads();
    float inv = 1.0f / red[1];

    float4 o4 = { e0 * inv, e1 * inv, e2 * inv, e3 * inv };
    ((float4*)p)[t] = o4;
}

// ------------------------- attn @ V (output rounded to tf32) -------------------------
__global__ void __launch_bounds__(256) attnv_k(
    const float* __restrict__ S, const float* __restrict__ qkv,
    float* __restrict__ out)
{
    __shared__ float Ps[16][68];
    __shared__ float Vs[16][68];
    int bh = blockIdx.z;
    int b = bh >> 4, h = bh & 15;
    int q0 = blockIdx.x * 64;
    int tid = threadIdx.x;
    int tx = tid & 15, ty = tid >> 4;

    float acc[4][4];
    #pragma unroll
    for (int i = 0; i < 4; i++)
        #pragma unroll
        for (int j = 0; j < 4; j++) acc[i][j] = 0.f;

    const float* Srow = S + ((size_t)bh * NSEQ + q0) * NSEQ;
    int prow = tid >> 2, pcol = (tid & 3) * 4;
    int vrow = tid >> 4, vcol = (tid & 15) * 4;

    for (int kk = 0; kk < NSEQ; kk += 16) {
        float4 p4 = *(const float4*)(Srow + (size_t)prow * NSEQ + kk + pcol);
        Ps[pcol + 0][prow] = p4.x;
        Ps[pcol + 1][prow] = p4.y;
        Ps[pcol + 2][prow] = p4.z;
        Ps[pcol + 3][prow] = p4.w;
        float4 v4 = *(const float4*)(qkv + (size_t)(b*NSEQ + kk + vrow)*3*DIMC + 2*DIMC + h*HD + vcol);
        *(float4*)&Vs[vrow][vcol] = v4;
        __syncthreads();

        #pragma unroll
        for (int k = 0; k < 16; k++) {
            float pa[4], va[4];
            #pragma unroll
            for (int i = 0; i < 4; i++) pa[i] = Ps[k][ty * 4 + i];
            #pragma unroll
            for (int j = 0; j < 4; j++) va[j] = Vs[k][tx * 4 + j];
            #pragma unroll
            for (int i = 0; i < 4; i++)
                #pragma unroll
                for (int j = 0; j < 4; j++)
                    acc[i][j] += pa[i] * va[j];
        }
        __syncthreads();
    }

    #pragma unroll
    for (int i = 0; i < 4; i++) {
        int qg = q0 + ty * 4 + i;
        #pragma unroll
        for (int j = 0; j < 4; j++) {
            int dg = tx * 4 + j;
            out[(size_t)(b * NSEQ + qg) * DIMC + h * HD + dg] = to_tf32(acc[i][j]);
        }
    }
}

// ------------------------- launch -------------------------
extern "C" void kernel_launch(void* const* d_in, const int* in_sizes, int n_in,
                              void* d_out, int out_size)
{
    const float* x      = (const float*)d_in[0];
    const int*   mask   = (const int*)  d_in[1];
    const float* ln1_g  = (const float*)d_in[2];
    const float* ln1_b  = (const float*)d_in[3];
    const float* qkv_w  = (const float*)d_in[4];
    const float* qkv_b  = (const float*)d_in[5];
    const float* proj_w = (const float*)d_in[6];
    const float* proj_b = (const float*)d_in[7];
    const float* rel    = (const float*)d_in[8];
    const float* ln2_g  = (const float*)d_in[9];
    const float* ln2_b  = (const float*)d_in[10];
    const float* mlp_w1 = (const float*)d_in[11];
    const float* mlp_b1 = (const float*)d_in[12];
    const float* mlp_w2 = (const float*)d_in[13];
    const float* mlp_b2 = (const float*)d_in[14];
    const float* gate1  = (const float*)d_in[15];
    const float* gate2  = (const float*)d_in[16];
    float* out = (float*)d_out;

    float *h1, *qkvbuf, *sc, *ao, *x1, *h2, *mlp, *wr;
    cudaGetSymbolAddress((void**)&h1,     g_h1);
    cudaGetSymbolAddress((void**)&qkvbuf, g_qkvbuf);
    cudaGetSymbolAddress((void**)&sc,     g_scores);
    cudaGetSymbolAddress((void**)&ao,     g_attnout);
    cudaGetSymbolAddress((void**)&x1,     g_x1);
    cudaGetSymbolAddress((void**)&h2,     g_h2);
    cudaGetSymbolAddress((void**)&mlp,    g_mlp);
    cudaGetSymbolAddress((void**)&wr,     g_wr);

    cudaFuncSetAttribute(wgemm_k<0>, cudaFuncAttributeMaxDynamicSharedMemorySize, SMEM_BYTES);
    cudaFuncSetAttribute(wgemm_k<1>, cudaFuncAttributeMaxDynamicSharedMemorySize, SMEM_BYTES);
    cudaFuncSetAttribute(wgemm_k<2>, cudaFuncAttributeMaxDynamicSharedMemorySize, SMEM_BYTES);

    // 0. round weights to tf32 scratch (removes cvt from GEMM mainloop)
    round_k<<<DIMC*3*DIMC/1024, 256>>>(qkv_w,  wr + WR_QKV);
    round_k<<<DIMC*DIMC/1024,   256>>>(proj_w, wr + WR_PROJ);
    round_k<<<DIMC*4*DIMC/1024, 256>>>(mlp_w1, wr + WR_W1);
    round_k<<<4*DIMC*DIMC/1024, 256>>>(mlp_w2, wr + WR_W2);

    // 1. LN1 (tf32-rounded output)
    layernorm_k<<<TOK, 256>>>(x, ln1_g, ln1_b, h1);
    // 2. QKV GEMM
    wgemm_k<0><<<dim3(3*DIMC/128, TOK/128), 256, SMEM_BYTES>>>(h1, wr + WR_QKV, qkv_b, nullptr, nullptr,
                                                               qkvbuf, TOK, 3*DIMC, DIMC);
    // 3. scores
    attn_scores_k<<<dim3(NSEQ/64, NSEQ/64, BATCH*HEADS), 256>>>(qkvbuf, rel, mask, sc);
    // 4. softmax
    softmax_k<<<BATCH*HEADS*NSEQ, 256>>>(sc);
    // 5. P @ V (tf32-rounded output)
    attnv_k<<<dim3(NSEQ/64, 1, BATCH*HEADS), 256>>>(sc, qkvbuf, ao);
    // 6. proj + residual (gate1)
    wgemm_k<2><<<dim3(DIMC/128, TOK/128), 256, SMEM_BYTES>>>(ao, wr + WR_PROJ, proj_b, x, gate1,
                                                             x1, TOK, DIMC, DIMC);
    // 7. LN2 (tf32-rounded output)
    layernorm_k<<<TOK, 256>>>(x1, ln2_g, ln2_b, h2);
    // 8. MLP1 + GELU (tf32-rounded output)
    wgemm_k<1><<<dim3(4*DIMC/128, TOK/128), 256, SMEM_BYTES>>>(h2, wr + WR_W1, mlp_b1, nullptr, nullptr,
                                                               mlp, TOK, 4*DIMC, DIMC);
    // 9. MLP2 + residual (gate2) -> out
    wgemm_k<2><<<dim3(DIMC/128, TOK/128), 256, SMEM_BYTES>>>(mlp, wr + WR_W2, mlp_b2, x1, gate2,
                                                             out, TOK, DIMC, 4*DIMC);
}

// round 14
// speedup vs baseline: 1.5687x; 1.1449x over previous
#include <cuda_runtime.h>
#include <cstdint>
#include <math.h>
#include <mma.h>

using namespace nvcuda;

#define DIMC   1024
#define HEADS  16
#define HD     64
#define NSEQ   1024
#define BATCH  4
#define TOK    (BATCH*NSEQ)

// GEMM tiling
#define BK       32
#define A_LD     36
#define B_LD     132
#define STAGE_F  (128*A_LD + BK*B_LD)
#define SMEM_BYTES (2*STAGE_F*4)

// flash attention smem: Qs,Ks,Vs,Ps,Os (64x72 fp32 each) + rels + mask
#define ALD       72
#define ATT_TILE  (64*ALD)
#define ATT_SMEM  (5*ATT_TILE*4 + 128*4 + 64*4)

// ------------------------- scratch (device globals) -------------------------
__device__ float g_h1[TOK*DIMC];
__device__ float g_qkvbuf[(size_t)TOK*3*DIMC];
__device__ float g_attnout[TOK*DIMC];
__device__ float g_x1[TOK*DIMC];
__device__ float g_h2[TOK*DIMC];
__device__ float g_mlp[(size_t)TOK*4*DIMC];
__device__ float g_wr[12582912];   // tf32-rounded weights: qkv|proj|w1|w2

#define WR_QKV  0
#define WR_PROJ 3145728
#define WR_W1   4194304
#define WR_W2   8388608

__device__ __forceinline__ float to_tf32(float x) {
    float r;
    asm("cvt.rna.tf32.f32 %0, %1;" : "=f"(r) : "f"(x));
    return r;
}

__device__ __forceinline__ void cp_async16(uint32_t dst, const void* src) {
    asm volatile("cp.async.cg.shared.global [%0], [%1], 16;" :: "r"(dst), "l"(src));
}
__device__ __forceinline__ void cp_commit() {
    asm volatile("cp.async.commit_group;");
}
template<int N>
__device__ __forceinline__ void cp_wait() {
    asm volatile("cp.async.wait_group %0;" :: "n"(N));
}

// ------------------------- tf32 rounding copy (weights, once per replay) -------------------------
__global__ void round_k(const float* __restrict__ src, float* __restrict__ dst)
{
    int i = blockIdx.x * 256 + threadIdx.x;
    float4 v = ((const float4*)src)[i];
    v.x = to_tf32(v.x); v.y = to_tf32(v.y); v.z = to_tf32(v.z); v.w = to_tf32(v.w);
    ((float4*)dst)[i] = v;
}

// ------------------------- layernorm (output rounded to tf32) -------------------------
__global__ void layernorm_k(const float* __restrict__ in,
                            const float* __restrict__ g,
                            const float* __restrict__ b,
                            float* __restrict__ out)
{
    __shared__ float red[32];
    int row = blockIdx.x;
    int t   = threadIdx.x;
    const float4* inr = (const float4*)(in + (size_t)row*DIMC);
    float4 v = inr[t];

    float s = v.x + v.y + v.z + v.w;
    #pragma unroll
    for (int o = 16; o > 0; o >>= 1) s += __shfl_xor_sync(0xffffffffu, s, o);
    if ((t & 31) == 0) red[t >> 5] = s;
    __syncthreads();
    if (t < 32) {
        float x = (t < 8) ? red[t] : 0.f;
        #pragma unroll
        for (int o = 4; o > 0; o >>= 1) x += __shfl_xor_sync(0xffffffffu, x, o);
        if (t == 0) red[0] = x;
    }
    __syncthreads();
    float mu = red[0] * (1.0f / DIMC);

    float d0 = v.x - mu, d1 = v.y - mu, d2 = v.z - mu, d3 = v.w - mu;
    float sq = d0*d0 + d1*d1 + d2*d2 + d3*d3;
    #pragma unroll
    for (int o = 16; o > 0; o >>= 1) sq += __shfl_xor_sync(0xffffffffu, sq, o);
    __syncthreads();
    if ((t & 31) == 0) red[t >> 5] = sq;
    __syncthreads();
    if (t < 32) {
        float x = (t < 8) ? red[t] : 0.f;
        #pragma unroll
        for (int o = 4; o > 0; o >>= 1) x += __shfl_xor_sync(0xffffffffu, x, o);
        if (t == 0) red[1] = x;
    }
    __syncthreads();
    float rstd = rsqrtf(red[1] * (1.0f / DIMC) + 1e-5f);

    float4 gv = ((const float4*)g)[t];
    float4 bv = ((const float4*)b)[t];
    float4 o4;
    o4.x = to_tf32(d0 * rstd * gv.x + bv.x);
    o4.y = to_tf32(d1 * rstd * gv.y + bv.y);
    o4.z = to_tf32(d2 * rstd * gv.z + bv.z);
    o4.w = to_tf32(d3 * rstd * gv.w + bv.w);
    ((float4*)(out + (size_t)row*DIMC))[t] = o4;
}

// ------------------------- tf32 WMMA GEMM, 128x128x32, cp.async double buffer -------------------------
template<int EPI>
__global__ void __launch_bounds__(256, 2) wgemm_k(
    const float* __restrict__ A, const float* __restrict__ W,
    const float* __restrict__ bias, const float* __restrict__ resid,
    const float* __restrict__ gate, float* __restrict__ C,
    int M, int Nn, int K)
{
    extern __shared__ float smem[];
    uint32_t sbase = (uint32_t)__cvta_generic_to_shared(smem);

    int tid  = threadIdx.x;
    int warp = tid >> 5;
    int lane = tid & 31;
    int wm = warp >> 1;
    int wn = warp & 1;
    int rowBase = blockIdx.y * 128;
    int colBase = blockIdx.x * 128;

    wmma::fragment<wmma::accumulator, 16, 16, 8, float> fc[2][4];
    #pragma unroll
    for (int i = 0; i < 2; i++)
        #pragma unroll
        for (int j = 0; j < 4; j++)
            wmma::fill_fragment(fc[i][j], 0.0f);

    int ar[4], ac[4], br4[4], bc4[4];
    #pragma unroll
    for (int i = 0; i < 4; i++) {
        int c = tid + i * 256;
        ar[i] = c >> 3;
        ac[i] = (c & 7) * 4;
        br4[i] = c >> 5;
        bc4[i] = (c & 31) * 4;
    }

    const int T = K / BK;

    {
        #pragma unroll
        for (int i = 0; i < 4; i++) {
            cp_async16(sbase + (ar[i]*A_LD + ac[i])*4,
                       A + (size_t)(rowBase + ar[i]) * K + ac[i]);
        }
        #pragma unroll
        for (int i = 0; i < 4; i++) {
            cp_async16(sbase + (128*A_LD + br4[i]*B_LD + bc4[i])*4,
                       W + (size_t)br4[i] * Nn + colBase + bc4[i]);
        }
        cp_commit();
    }

    for (int t = 0; t < T; t++) {
        int cur = t & 1;
        if (t + 1 < T) {
            int k0 = (t + 1) * BK;
            uint32_t stg = sbase + (uint32_t)(((t + 1) & 1) * STAGE_F * 4);
            #pragma unroll
            for (int i = 0; i < 4; i++) {
                cp_async16(stg + (ar[i]*A_LD + ac[i])*4,
                           A + (size_t)(rowBase + ar[i]) * K + k0 + ac[i]);
            }
            #pragma unroll
            for (int i = 0; i < 4; i++) {
                cp_async16(stg + (128*A_LD + br4[i]*B_LD + bc4[i])*4,
                           W + (size_t)(k0 + br4[i]) * Nn + colBase + bc4[i]);
            }
            cp_commit();
            cp_wait<1>();
        } else {
            cp_commit();
            cp_wait<0>();
        }
        __syncthreads();

        const float* As = smem + cur * STAGE_F;
        const float* Bs = As + 128 * A_LD;

        #pragma unroll
        for (int ks = 0; ks < BK; ks += 8) {
            wmma::fragment<wmma::matrix_a, 16, 16, 8, wmma::precision::tf32, wmma::row_major> fa[2];
            wmma::fragment<wmma::matrix_b, 16, 16, 8, wmma::precision::tf32, wmma::row_major> fb[4];
            #pragma unroll
            for (int i = 0; i < 2; i++)
                wmma::load_matrix_sync(fa[i], As + (wm*32 + i*16)*A_LD + ks, A_LD);
            #pragma unroll
            for (int j = 0; j < 4; j++)
                wmma::load_matrix_sync(fb[j], Bs + ks*B_LD + wn*64 + j*16, B_LD);
            #pragma unroll
            for (int i = 0; i < 2; i++)
                #pragma unroll
                for (int j = 0; j < 4; j++)
                    wmma::mma_sync(fc[i][j], fa[i], fb[j], fc[i][j]);
        }
        __syncthreads();
    }

    float* stage = smem + warp * 320;
    float gv = (EPI == 2) ? gate[0] : 0.f;
    int rr = lane >> 1;
    int cc = (lane & 1) * 8;
    #pragma unroll
    for (int i = 0; i < 2; i++) {
        #pragma unroll
        for (int j = 0; j < 4; j++) {
            wmma::store_matrix_sync(stage, fc[i][j], 20, wmma::mem_row_major);
            __syncwarp();
            int grow = rowBase + wm*32 + i*16 + rr;
            int gcol = colBase + wn*64 + j*16 + cc;
            #pragma unroll
            for (int u = 0; u < 8; u++) {
                float v = stage[rr*20 + cc + u] + bias[gcol + u];
                if (EPI == 1) {
                    v = to_tf32(0.5f * v * (1.0f + erff(v * 0.70710678118654752f)));
                } else if (EPI == 2) {
                    v = resid[(size_t)grow * Nn + gcol + u] + gv * v;
                }
                C[(size_t)grow * Nn + gcol + u] = v;
            }
            __syncwarp();
        }
    }
}

// ------------------------- fused flash attention (wmma tf32) -------------------------
// grid (NSEQ/64, BATCH*HEADS), 256 threads. Output rounded to tf32 (proj GEMM input).
__global__ void __launch_bounds__(256) attn_flash_k(
    const float* __restrict__ qkv, const float* __restrict__ rel,
    const int* __restrict__ mask, float* __restrict__ out)
{
    extern __shared__ float sm[];
    float* Qs = sm;
    float* Ks = Qs + ATT_TILE;
    float* Vs = Ks + ATT_TILE;
    float* Ps = Vs + ATT_TILE;
    float* Os = Ps + ATT_TILE;
    float* rels = Os + ATT_TILE;           // 128
    int*   maskk = (int*)(rels + 128);     // 64

    uint32_t sb = (uint32_t)__cvta_generic_to_shared(sm);
    uint32_t Qa = sb;
    uint32_t Ka = Qa + ATT_TILE*4;
    uint32_t Va = Ka + ATT_TILE*4;

    int tid  = threadIdx.x;
    int warp = tid >> 5;
    int lane = tid & 31;
    int q0 = blockIdx.x * 64;
    int bh = blockIdx.y;
    int b = bh >> 4, h = bh & 15;

    // softmax ownership: row = warp*8 + (lane>>2), cols c0..c0+15
    int row = warp * 8 + (lane >> 2);
    int c0  = (lane & 3) * 16;
    float* Prow = Ps + row * ALD;
    float* Orow = Os + row * ALD;
    int   mqr = mask[b * NSEQ + q0 + row];
    float m_run = -1e30f, l_run = 0.f;

    // zero O rows
    #pragma unroll
    for (int j = 0; j < 16; j += 4)
        *(float4*)(Orow + c0 + j) = make_float4(0.f, 0.f, 0.f, 0.f);

    // load Q (64x64 fp32) into Qs
    {
        const float* src = qkv + (size_t)(b*NSEQ + q0) * 3*DIMC + h*HD;
        #pragma unroll
        for (int i = 0; i < 4; i++) {
            int c = tid + i * 256;
            int r = c >> 4, f4 = c & 15;
            cp_async16(Qa + (uint32_t)(r * ALD * 4 + f4 * 16),
                       src + (size_t)r * 3*DIMC + f4 * 4);
        }
        cp_commit();
    }

    typedef wmma::fragment<wmma::matrix_a, 16, 16, 8, wmma::precision::tf32, wmma::row_major> FragA;
    typedef wmma::fragment<wmma::matrix_b, 16, 16, 8, wmma::precision::tf32, wmma::col_major> FragBc;
    typedef wmma::fragment<wmma::matrix_b, 16, 16, 8, wmma::precision::tf32, wmma::row_major> FragBr;
    typedef wmma::fragment<wmma::accumulator, 16, 16, 8, float> FragC;

    for (int kb = 0; kb < NSEQ/64; kb++) {
        int k0 = kb * 64;
        // issue K then V loads
        {
            const float* srcK = qkv + (size_t)(b*NSEQ + k0) * 3*DIMC + DIMC + h*HD;
            #pragma unroll
            for (int i = 0; i < 4; i++) {
                int c = tid + i * 256;
                int r = c >> 4, f4 = c & 15;
                cp_async16(Ka + (uint32_t)(r * ALD * 4 + f4 * 16),
                           srcK + (size_t)r * 3*DIMC + f4 * 4);
            }
            cp_commit();
            const float* srcV = qkv + (size_t)(b*NSEQ + k0) * 3*DIMC + 2*DIMC + h*HD;
            #pragma unroll
            for (int i = 0; i < 4; i++) {
                int c = tid + i * 256;
                int r = c >> 4, f4 = c & 15;
                cp_async16(Va + (uint32_t)(r * ALD * 4 + f4 * 16),
                           srcV + (size_t)r * 3*DIMC + f4 * 4);
            }
            cp_commit();
        }
        // rel bias slice + k-mask for this block
        if (tid < 127) rels[tid] = rel[(size_t)(q0 - k0 + 960 + tid) * HEADS + h];
        if (tid < 64)  maskk[tid] = mask[b * NSEQ + k0 + tid];

        cp_wait<1>();          // K (and Q on first block) arrived
        __syncthreads();

        // S = Q @ K^T  -> Ps
        #pragma unroll
        for (int t = warp; t < 16; t += 8) {
            int rw = t >> 2, cw = t & 3;
            FragC acc;
            wmma::fill_fragment(acc, 0.0f);
            #pragma unroll
            for (int d = 0; d < HD; d += 8) {
                FragA fa;
                FragBc fb;
                wmma::load_matrix_sync(fa, Qs + rw*16*ALD + d, ALD);
                wmma::load_matrix_sync(fb, Ks + cw*16*ALD + d, ALD);
                wmma::mma_sync(acc, fa, fb, acc);
            }
            wmma::store_matrix_sync(Ps + rw*16*ALD + cw*16, acc, ALD, wmma::mem_row_major);
        }
        __syncthreads();

        // online softmax on rows (SIMT)
        {
            float vals[16];
            float mx = -1e30f;
            #pragma unroll
            for (int j4 = 0; j4 < 4; j4++) {
                float4 sv = *(float4*)(Prow + c0 + j4*4);
                float vv[4] = { sv.x, sv.y, sv.z, sv.w };
                #pragma unroll
                for (int u = 0; u < 4; u++) {
                    int k = c0 + j4*4 + u;
                    float s = vv[u] * 0.125f + rels[row - k + 63];
                    s = (mqr && maskk[k]) ? s : -1e9f;
                    vals[j4*4 + u] = s;
                    mx = fmaxf(mx, s);
                }
            }
            mx = fmaxf(mx, __shfl_xor_sync(0xffffffffu, mx, 1));
            mx = fmaxf(mx, __shfl_xor_sync(0xffffffffu, mx, 2));
            float m_new = fmaxf(m_run, mx);
            float corr = __expf(m_run - m_new);
            float ss = 0.f;
            #pragma unroll
            for (int j4 = 0; j4 < 4; j4++) {
                float4 pv;
                pv.x = __expf(vals[j4*4+0] - m_new);
                pv.y = __expf(vals[j4*4+1] - m_new);
                pv.z = __expf(vals[j4*4+2] - m_new);
                pv.w = __expf(vals[j4*4+3] - m_new);
                ss += pv.x + pv.y + pv.z + pv.w;
                *(float4*)(Prow + c0 + j4*4) = pv;
            }
            ss += __shfl_xor_sync(0xffffffffu, ss, 1);
            ss += __shfl_xor_sync(0xffffffffu, ss, 2);
            l_run = l_run * corr + ss;
            m_run = m_new;
            // rescale O row
            #pragma unroll
            for (int j4 = 0; j4 < 4; j4++) {
                float4 ov = *(float4*)(Orow + c0 + j4*4);
                ov.x *= corr; ov.y *= corr; ov.z *= corr; ov.w *= corr;
                *(float4*)(Orow + c0 + j4*4) = ov;
            }
        }

        cp_wait<0>();          // V arrived
        __syncthreads();       // Ps/Os updates visible, Vs ready

        // O += P @ V
        #pragma unroll
        for (int t = warp; t < 16; t += 8) {
            int rw = t >> 2, cw = t & 3;
            FragC acc;
            wmma::load_matrix_sync(acc, Os + rw*16*ALD + cw*16, ALD, wmma::mem_row_major);
            #pragma unroll
            for (int kk = 0; kk < 64; kk += 8) {
                FragA fa;
                FragBr fb;
                wmma::load_matrix_sync(fa, Ps + rw*16*ALD + kk, ALD);
                wmma::load_matrix_sync(fb, Vs + kk*ALD + cw*16, ALD);
                wmma::mma_sync(acc, fa, fb, acc);
            }
            wmma::store_matrix_sync(Os + rw*16*ALD + cw*16, acc, ALD, wmma::mem_row_major);
        }
        __syncthreads();
    }

    // normalize + write (tf32 rounded, input to proj GEMM)
    float inv = 1.0f / l_run;
    float* dst = out + (size_t)(b*NSEQ + q0 + row) * DIMC + h*HD;
    #pragma unroll
    for (int j = 0; j < 16; j++)
        dst[c0 + j] = to_tf32(Orow[c0 + j] * inv);
}

// ------------------------- launch -------------------------
extern "C" void kernel_launch(void* const* d_in, const int* in_sizes, int n_in,
                              void* d_out, int out_size)
{
    const float* x      = (const float*)d_in[0];
    const int*   mask   = (const int*)  d_in[1];
    const float* ln1_g  = (const float*)d_in[2];
    const float* ln1_b  = (const float*)d_in[3];
    const float* qkv_w  = (const float*)d_in[4];
    const float* qkv_b  = (const float*)d_in[5];
    const float* proj_w = (const float*)d_in[6];
    const float* proj_b = (const float*)d_in[7];
    const float* rel    = (const float*)d_in[8];
    const float* ln2_g  = (const float*)d_in[9];
    const float* ln2_b  = (const float*)d_in[10];
    const float* mlp_w1 = (const float*)d_in[11];
    const float* mlp_b1 = (const float*)d_in[12];
    const float* mlp_w2 = (const float*)d_in[13];
    const float* mlp_b2 = (const float*)d_in[14];
    const float* gate1  = (const float*)d_in[15];
    const float* gate2  = (const float*)d_in[16];
    float* out = (float*)d_out;

    float *h1, *qkvbuf, *ao, *x1, *h2, *mlp, *wr;
    cudaGetSymbolAddress((void**)&h1,     g_h1);
    cudaGetSymbolAddress((void**)&qkvbuf, g_qkvbuf);
    cudaGetSymbolAddress((void**)&ao,     g_attnout);
    cudaGetSymbolAddress((void**)&x1,     g_x1);
    cudaGetSymbolAddress((void**)&h2,     g_h2);
    cudaGetSymbolAddress((void**)&mlp,    g_mlp);
    cudaGetSymbolAddress((void**)&wr,     g_wr);

    cudaFuncSetAttribute(wgemm_k<0>, cudaFuncAttributeMaxDynamicSharedMemorySize, SMEM_BYTES);
    cudaFuncSetAttribute(wgemm_k<1>, cudaFuncAttributeMaxDynamicSharedMemorySize, SMEM_BYTES);
    cudaFuncSetAttribute(wgemm_k<2>, cudaFuncAttributeMaxDynamicSharedMemorySize, SMEM_BYTES);
    cudaFuncSetAttribute(attn_flash_k, cudaFuncAttributeMaxDynamicSharedMemorySize, ATT_SMEM);

    // 0. round weights to tf32 scratch
    round_k<<<DIMC*3*DIMC/1024, 256>>>(qkv_w,  wr + WR_QKV);
    round_k<<<DIMC*DIMC/1024,   256>>>(proj_w, wr + WR_PROJ);
    round_k<<<DIMC*4*DIMC/1024, 256>>>(mlp_w1, wr + WR_W1);
    round_k<<<4*DIMC*DIMC/1024, 256>>>(mlp_w2, wr + WR_W2);

    // 1. LN1
    layernorm_k<<<TOK, 256>>>(x, ln1_g, ln1_b, h1);
    // 2. QKV GEMM
    wgemm_k<0><<<dim3(3*DIMC/128, TOK/128), 256, SMEM_BYTES>>>(h1, wr + WR_QKV, qkv_b, nullptr, nullptr,
                                                               qkvbuf, TOK, 3*DIMC, DIMC);
    // 3. fused flash attention -> attnout
    attn_flash_k<<<dim3(NSEQ/64, BATCH*HEADS), 256, ATT_SMEM>>>(qkvbuf, rel, mask, ao);
    // 4. proj + residual (gate1)
    wgemm_k<2><<<dim3(DIMC/128, TOK/128), 256, SMEM_BYTES>>>(ao, wr + WR_PROJ, proj_b, x, gate1,
                                                             x1, TOK, DIMC, DIMC);
    // 5. LN2
    layernorm_k<<<TOK, 256>>>(x1, ln2_g, ln2_b, h2);
    // 6. MLP1 + GELU
    wgemm_k<1><<<dim3(4*DIMC/128, TOK/128), 256, SMEM_BYTES>>>(h2, wr + WR_W1, mlp_b1, nullptr, nullptr,
                                                               mlp, TOK, 4*DIMC, DIMC);
    // 7. MLP2 + residual (gate2) -> out
    wgemm_k<2><<<dim3(DIMC/128, TOK/128), 256, SMEM_BYTES>>>(mlp, wr + WR_W2, mlp_b2, x1, gate2,
                                                             out, TOK, DIMC, 4*DIMC);
}